// round 3
// baseline (speedup 1.0000x reference)
#include <cuda_runtime.h>
#include <math.h>

// Problem dims
#define BB  32      // batch
#define SS  100     // src len
#define TT  64      // trg len
#define HH  512     // hidden
#define EE  512     // embed
#define VV  32000   // vocab
#define G4H 2048    // 4*H
#define KZ  1536    // 2E + H (fused gate input)

// ---------------- device scratch (static globals; no runtime alloc) ----------------
__device__ float g_W4[G4H * KZ];     // fused [W_ih | W_hh], rows reordered to 4*h+gate
__device__ float g_b4[G4H];          // fused bias, same reorder
__device__ float g_Wqb[HH * HH];     // Wb @ Wq
__device__ float g_bqb[HH];          // Wb @ bq + bb
__device__ float g_h[2][BB * HH];    // hidden ping-pong
__device__ float g_c[BB * HH];       // cell
__device__ float g_qb[BB * HH];      // bilinear query
__device__ float g_ctx[BB * HH];     // attention context
__device__ float g_u[BB * HH];       // tanh(MLP) intermediate
__device__ float g_out[TT * BB * EE];// all decoder outputs (T,B,E) for deferred logits GEMM
__device__ int   g_trg64;            // 1 if trg buffer is int64
__device__ int   g_maskty;           // 0=uint8, 1=int32, 2=float32

// ---------------- dtype detection (graph-safe, runs every call) ----------------
// trg: int64 buffers have all-zero odd int32 words (tokens < 32000). We only read
// the first BB*TT int32 words, which is within bounds for BOTH widths.
// mask: int32 all-{0,1} words -> int32; {0, 0x3f800000} -> float32; else uint8
// (uint8 ones pack to 0x01010101). Reads first BB*SS/4 words: within bounds for all.
__global__ void detect_types(const int* __restrict__ trg_w, const int* __restrict__ mask_w) {
    __shared__ int s_odd_nz, s_bin, s_f32;
    if (threadIdx.x == 0) { s_odd_nz = 0; s_bin = 1; s_f32 = 1; }
    __syncthreads();
    for (int i = threadIdx.x; i < (BB * TT) / 2; i += blockDim.x)
        if (trg_w[2 * i + 1] != 0) atomicOr(&s_odd_nz, 1);
    for (int i = threadIdx.x; i < (BB * SS) / 4; i += blockDim.x) {
        int v = mask_w[i];
        if (v != 0 && v != 1)           atomicAnd(&s_bin, 0);
        if (v != 0 && v != 0x3f800000)  atomicAnd(&s_f32, 0);
    }
    __syncthreads();
    if (threadIdx.x == 0) {
        g_trg64 = s_odd_nz ? 0 : 1;
        g_maskty = s_bin ? 1 : (s_f32 ? 2 : 0);
    }
}

// ---------------- prep kernels ----------------

// Build fused/reordered gate weights: out row rr = 4*h + g  <-  orig row j = g*H + h
__global__ void prep_w4(const float* __restrict__ Wih, const float* __restrict__ Whh,
                        const float* __restrict__ bih, const float* __restrict__ bhh) {
    int rr = blockIdx.x;              // 0..2047
    int h = rr >> 2, g = rr & 3;
    int j = g * HH + h;
    for (int k = threadIdx.x; k < KZ; k += blockDim.x) {
        float v = (k < 2 * EE) ? Wih[j * (2 * EE) + k] : Whh[j * HH + (k - 2 * EE)];
        g_W4[rr * KZ + k] = v;
    }
    if (threadIdx.x == 0) g_b4[rr] = bih[j] + bhh[j];
}

// Wqb = Wb @ Wq ;  bqb = Wb @ bq + bb
__global__ void prep_wqb(const float* __restrict__ Wq, const float* __restrict__ Wb,
                         const float* __restrict__ bq, const float* __restrict__ bbias) {
    int r = blockIdx.y * 16 + threadIdx.y;
    int c = blockIdx.x * 16 + threadIdx.x;
    float acc = 0.f;
    for (int k = 0; k < HH; k++) acc += Wb[r * HH + k] * Wq[k * HH + c];
    g_Wqb[r * HH + c] = acc;
    if (blockIdx.x == 0 && threadIdx.x == 0) {
        float a = bbias[r];
        for (int k = 0; k < HH; k++) a += Wb[r * HH + k] * bq[k];
        g_bqb[r] = a;
    }
}

__global__ void prep_init(const float* __restrict__ ih, const float* __restrict__ ic) {
    int i = blockIdx.x * 256 + threadIdx.x;
    if (i < BB * HH) { g_h[0][i] = ih[i]; g_c[i] = ic[i]; }
}

// ---------------- per-step kernel 1: gates GEMM + LSTM elementwise ----------------
// Block = 256 thr, handles 16 gate rows (4 hiddens) x all 32 batches. Grid = 128.
__global__ void __launch_bounds__(256) lstm_gates(
    const float* __restrict__ emb, const void* __restrict__ trg_raw, int t,
    const float* __restrict__ out_prev, const float* __restrict__ h_prev,
    float* __restrict__ h_out)
{
    __shared__ float Zs[64][33];
    __shared__ float Ws[16][64];
    __shared__ float Gs[16][33];
    __shared__ int   tok[BB];

    int tid = threadIdx.x, w = tid >> 5, l = tid & 31;
    int hg = blockIdx.x;           // hidden group 0..127 (4 hiddens each)
    int rbase = hg * 16;

    if (tid < BB) {
        long long v;
        if (g_trg64) v = ((const long long*)trg_raw)[tid * TT + t];
        else         v = ((const int*)trg_raw)[tid * TT + t];
        int tk = (int)v;
        if (tk < 0) tk = 0;
        if (tk >= VV) tk = VV - 1;
        tok[tid] = tk;
    }
    __syncthreads();

    float acc0 = 0.f, acc1 = 0.f;
    for (int kt = 0; kt < KZ / 64; kt++) {
        int kg0 = kt * 64;
        // Z tile: coalesced along k, transposed store (padded to kill conflicts)
        for (int i = tid; i < 2048; i += 256) {
            int b = i >> 6, k = i & 63, kg = kg0 + k;
            float v;
            if      (kg < EE)      v = emb[(size_t)tok[b] * EE + kg];
            else if (kg < 2 * EE)  v = out_prev[b * EE + (kg - EE)];
            else                   v = h_prev[b * HH + (kg - 2 * EE)];
            Zs[k][b] = v;
        }
        // W tile
        for (int i = tid; i < 1024; i += 256) {
            int r = i >> 6, k = i & 63;
            Ws[r][k] = g_W4[(rbase + r) * KZ + kg0 + k];
        }
        __syncthreads();
        #pragma unroll
        for (int kk = 0; kk < 64; kk++) {
            float z = Zs[kk][l];
            acc0 += Ws[w][kk] * z;
            acc1 += Ws[w + 8][kk] * z;
        }
        __syncthreads();
    }
    Gs[w][l]     = acc0 + g_b4[rbase + w];
    Gs[w + 8][l] = acc1 + g_b4[rbase + w + 8];
    __syncthreads();

    if (tid < 128) {
        int hl = tid >> 5, b = tid & 31;
        float gi = Gs[4 * hl + 0][b];
        float gf = Gs[4 * hl + 1][b];
        float gg = Gs[4 * hl + 2][b];
        float go = Gs[4 * hl + 3][b];
        gi = 1.f / (1.f + expf(-gi));
        gf = 1.f / (1.f + expf(-gf));
        go = 1.f / (1.f + expf(-go));
        gg = tanhf(gg);
        int h = hg * 4 + hl;
        int idx = b * HH + h;
        float c = gf * g_c[idx] + gi * gg;
        g_c[idx] = c;
        h_out[idx] = go * tanhf(c);
    }
}

// ---------------- generic small GEMM: out(32,M) = Z(32,Ktot) @ W(M,Ktot)^T + bias ----------------
// Z = concat(Z0[:,K0], Z1[:,Ktot-K0]). Block: 16 rows x 32 batches. act: 0=none, 1=tanh.
__global__ void __launch_bounds__(256) gemm16(
    const float* __restrict__ W, const float* __restrict__ bias,
    const float* __restrict__ Z0, int K0,
    const float* __restrict__ Z1, int Ktot,
    float* __restrict__ outp, int M, int act)
{
    __shared__ float Zs[64][33];
    __shared__ float Ws[16][64];
    int tid = threadIdx.x, w = tid >> 5, l = tid & 31;
    int rbase = blockIdx.x * 16;

    float acc0 = 0.f, acc1 = 0.f;
    for (int kt = 0; kt < Ktot / 64; kt++) {
        int kg0 = kt * 64;
        for (int i = tid; i < 2048; i += 256) {
            int b = i >> 6, k = i & 63, kg = kg0 + k;
            float v = (kg < K0) ? Z0[b * K0 + kg] : Z1[b * (Ktot - K0) + (kg - K0)];
            Zs[k][b] = v;
        }
        for (int i = tid; i < 1024; i += 256) {
            int r = i >> 6, k = i & 63;
            Ws[r][k] = W[(rbase + r) * Ktot + kg0 + k];
        }
        __syncthreads();
        #pragma unroll
        for (int kk = 0; kk < 64; kk++) {
            float z = Zs[kk][l];
            acc0 += Ws[w][kk] * z;
            acc1 += Ws[w + 8][kk] * z;
        }
        __syncthreads();
    }
    acc0 += bias[rbase + w];
    acc1 += bias[rbase + w + 8];
    if (act) { acc0 = tanhf(acc0); acc1 = tanhf(acc1); }
    outp[l * M + rbase + w]     = acc0;
    outp[l * M + rbase + w + 8] = acc1;
}

// ---------------- attention: scores -> masked softmax -> ctx ----------------
__global__ void __launch_bounds__(256) attention(
    const float* __restrict__ mem, const void* __restrict__ mask_raw)
{
    int b = blockIdx.x, tid = threadIdx.x, w = tid >> 5, l = tid & 31;
    __shared__ float q[HH];
    __shared__ float sc[SS];

    for (int i = tid; i < HH; i += 256) q[i] = g_qb[b * HH + i];
    __syncthreads();

    int mty = g_maskty;
    for (int s = w; s < SS; s += 8) {
        const float* mrow = mem + (size_t)(b * SS + s) * HH;
        float a = 0.f;
        for (int k = l; k < HH; k += 32) a += q[k] * mrow[k];
        #pragma unroll
        for (int off = 16; off; off >>= 1) a += __shfl_down_sync(0xffffffffu, a, off);
        if (l == 0) {
            int mi = b * SS + s;
            bool mv;
            if      (mty == 0) mv = ((const unsigned char*)mask_raw)[mi] != 0;
            else if (mty == 1) mv = ((const int*)mask_raw)[mi] != 0;
            else               mv = ((const float*)mask_raw)[mi] != 0.0f;
            sc[s] = mv ? a : -1e9f;
        }
    }
    __syncthreads();

    if (w == 0) {
        float m = -1e30f;
        for (int s = l; s < SS; s += 32) m = fmaxf(m, sc[s]);
        #pragma unroll
        for (int off = 16; off; off >>= 1) m = fmaxf(m, __shfl_xor_sync(0xffffffffu, m, off));
        float sum = 0.f;
        for (int s = l; s < SS; s += 32) { float e = expf(sc[s] - m); sc[s] = e; sum += e; }
        #pragma unroll
        for (int off = 16; off; off >>= 1) sum += __shfl_xor_sync(0xffffffffu, sum, off);
        float inv = 1.f / sum;
        for (int s = l; s < SS; s += 32) sc[s] *= inv;
    }
    __syncthreads();

    for (int h = tid; h < HH; h += 256) {
        float a = 0.f;
        #pragma unroll 4
        for (int s = 0; s < SS; s++) a += sc[s] * mem[(size_t)(b * SS + s) * HH + h];
        g_ctx[b * HH + h] = a;
    }
}

// ---------------- final big GEMM: logits(2048, 32000) = Out(2048,512) @ emb(32000,512)^T ----------
#define BM 128
#define BN 128
#define BKK 16
__global__ void __launch_bounds__(256) logits_gemm(
    const float* __restrict__ emb, float* __restrict__ outp)
{
    __shared__ float As[BKK][BM + 4];
    __shared__ float Bs[BKK][BN + 4];
    int tid = threadIdx.x;
    int tx = tid & 15, ty = tid >> 4;
    int mblk = blockIdx.y * BM;
    int nblk = blockIdx.x * BN;

    float acc[8][8];
    #pragma unroll
    for (int i = 0; i < 8; i++)
        #pragma unroll
        for (int j = 0; j < 8; j++) acc[i][j] = 0.f;

    for (int kt = 0; kt < EE / BKK; kt++) {
        int kb = kt * BKK;
        #pragma unroll
        for (int j = 0; j < 2; j++) {
            int f = tid * 2 + j;                 // 0..511 float4 slots
            int m = f >> 2, k4 = (f & 3) * 4;
            float4 v = *(const float4*)(g_out + (size_t)(mblk + m) * EE + kb + k4);
            As[k4 + 0][m] = v.x; As[k4 + 1][m] = v.y;
            As[k4 + 2][m] = v.z; As[k4 + 3][m] = v.w;
        }
        #pragma unroll
        for (int j = 0; j < 2; j++) {
            int f = tid * 2 + j;
            int n = f >> 2, k4 = (f & 3) * 4;
            float4 v = *(const float4*)(emb + (size_t)(nblk + n) * EE + kb + k4);
            Bs[k4 + 0][n] = v.x; Bs[k4 + 1][n] = v.y;
            Bs[k4 + 2][n] = v.z; Bs[k4 + 3][n] = v.w;
        }
        __syncthreads();
        #pragma unroll
        for (int k = 0; k < BKK; k++) {
            float a[8], bv[8];
            #pragma unroll
            for (int i = 0; i < 8; i++) a[i] = As[k][ty * 8 + i];
            #pragma unroll
            for (int i = 0; i < 8; i++) bv[i] = Bs[k][tx * 8 + i];
            #pragma unroll
            for (int i = 0; i < 8; i++)
                #pragma unroll
                for (int j = 0; j < 8; j++) acc[i][j] += a[i] * bv[j];
        }
        __syncthreads();
    }
    // row r = t*B + b ; output index = (b*T + t)*V + v
    #pragma unroll
    for (int i = 0; i < 8; i++) {
        int r = mblk + ty * 8 + i;
        int tt = r >> 5, bb = r & 31;
        float* orow = outp + (size_t)(bb * TT + tt) * VV + nblk + tx * 8;
        #pragma unroll
        for (int j = 0; j < 8; j++) orow[j] = acc[i][j];
    }
}

// ---------------- host launch ----------------
extern "C" void kernel_launch(void* const* d_in, const int* in_sizes, int n_in,
                              void* d_out, int out_size)
{
    const float* src_memory  = (const float*)d_in[0];
    const void*  src_mask    = d_in[1];
    const float* init_hidden = (const float*)d_in[2];
    const float* init_cell   = (const float*)d_in[3];
    const float* init_output = (const float*)d_in[4];
    const void*  trg         = d_in[5];
    const float* emb         = (const float*)d_in[6];
    const float* W_ih        = (const float*)d_in[7];
    const float* W_hh        = (const float*)d_in[8];
    const float* b_ih        = (const float*)d_in[9];
    const float* b_hh        = (const float*)d_in[10];
    const float* Wq          = (const float*)d_in[11];
    const float* bq          = (const float*)d_in[12];
    const float* Wb          = (const float*)d_in[13];
    const float* bbias       = (const float*)d_in[14];
    const float* Wo1         = (const float*)d_in[15];
    const float* bo1         = (const float*)d_in[16];
    const float* Wo2         = (const float*)d_in[17];
    const float* bo2         = (const float*)d_in[18];

    float *p_Wqb, *p_bqb, *p_h, *p_qb, *p_ctx, *p_u, *p_out;
    cudaGetSymbolAddress((void**)&p_Wqb, g_Wqb);
    cudaGetSymbolAddress((void**)&p_bqb, g_bqb);
    cudaGetSymbolAddress((void**)&p_h,   g_h);
    cudaGetSymbolAddress((void**)&p_qb,  g_qb);
    cudaGetSymbolAddress((void**)&p_ctx, g_ctx);
    cudaGetSymbolAddress((void**)&p_u,   g_u);
    cudaGetSymbolAddress((void**)&p_out, g_out);

    detect_types<<<1, 256>>>((const int*)trg, (const int*)src_mask);
    prep_w4<<<G4H, 256>>>(W_ih, W_hh, b_ih, b_hh);
    prep_wqb<<<dim3(32, 32), dim3(16, 16)>>>(Wq, Wb, bq, bbias);
    prep_init<<<(BB * HH + 255) / 256, 256>>>(init_hidden, init_cell);

    for (int t = 0; t < TT; t++) {
        const float* out_prev = (t == 0) ? init_output : (p_out + (size_t)(t - 1) * BB * EE);
        const float* h_prev = p_h + (t & 1) * BB * HH;
        float*       h_cur  = p_h + ((t + 1) & 1) * BB * HH;

        lstm_gates<<<128, 256>>>(emb, trg, t, out_prev, h_prev, h_cur);
        gemm16<<<HH / 16, 256>>>(p_Wqb, p_bqb, h_cur, HH, (const float*)0, HH, p_qb, HH, 0);
        attention<<<BB, 256>>>(src_memory, src_mask);
        gemm16<<<HH / 16, 256>>>(Wo1, bo1, h_cur, HH, p_ctx, 2 * HH, p_u, HH, 1);
        gemm16<<<HH / 16, 256>>>(Wo2, bo2, p_u, HH, (const float*)0, HH,
                                 p_out + (size_t)t * BB * EE, HH, 0);
    }

    logits_gemm<<<dim3(VV / BN, (TT * BB) / BM), 256>>>(emb, (float*)d_out);
}

// round 5
// speedup vs baseline: 1.0812x; 1.0812x over previous
#include <cuda_runtime.h>
#include <cuda_bf16.h>
#include <math.h>
#include <stdint.h>

// Problem dims
#define BB  32      // batch
#define SS  100     // src len
#define TT  64      // trg len
#define HH  512     // hidden
#define EE  512     // embed
#define VV  32000   // vocab
#define G4H 2048    // 4*H
#define KZ  1536    // 2E + H (fused gate input)

// ---------------- device scratch (static globals; no runtime alloc) ----------------
__device__ float g_W4[G4H * KZ];     // fused [W_ih | W_hh], rows reordered to 4*h+gate
__device__ float g_b4[G4H];          // fused bias, same reorder
__device__ float g_Wqb[HH * HH];     // Wb @ Wq
__device__ float g_bqb[HH];          // Wb @ bq + bb
__device__ float g_h[2][BB * HH];    // hidden ping-pong
__device__ float g_c[BB * HH];       // cell
__device__ float g_qb[BB * HH];      // bilinear query
__device__ float g_ctx[BB * HH];     // attention context
__device__ float g_u[BB * HH];       // tanh(MLP) intermediate
__device__ float g_out[TT * BB * EE];// all decoder outputs (T,B,E)
__device__ int   g_trg64;            // 1 if trg buffer is int64
__device__ int   g_maskty;           // 0=uint8, 1=int32, 2=float32

// bf16 hi/lo splits for tensor-core logits GEMM
__device__ unsigned short g_Bh[(size_t)VV * EE];  // emb hi
__device__ unsigned short g_Bl[(size_t)VV * EE];  // emb lo
__device__ unsigned short g_Ah[(size_t)TT * BB * EE]; // out hi
__device__ unsigned short g_Al[(size_t)TT * BB * EE]; // out lo

// ---------------- helpers ----------------
__device__ __forceinline__ uint32_t smem_u32(const void* p) {
    uint32_t a;
    asm("{ .reg .u64 t; cvta.to.shared.u64 t, %1; cvt.u32.u64 %0, t; }" : "=r"(a) : "l"(p));
    return a;
}

__device__ __forceinline__ void ldm_x4(uint32_t* r, uint32_t addr) {
    asm volatile("ldmatrix.sync.aligned.m8n8.x4.shared.b16 {%0,%1,%2,%3}, [%4];"
                 : "=r"(r[0]), "=r"(r[1]), "=r"(r[2]), "=r"(r[3]) : "r"(addr));
}

__device__ __forceinline__ void mma_bf16(float* d, const uint32_t* a, uint32_t b0, uint32_t b1) {
    asm volatile(
        "mma.sync.aligned.m16n8k16.row.col.f32.bf16.bf16.f32 "
        "{%0,%1,%2,%3}, {%4,%5,%6,%7}, {%8,%9}, {%0,%1,%2,%3};"
        : "+f"(d[0]), "+f"(d[1]), "+f"(d[2]), "+f"(d[3])
        : "r"(a[0]), "r"(a[1]), "r"(a[2]), "r"(a[3]), "r"(b0), "r"(b1));
}

// ---------------- dtype detection (graph-safe, runs every call) ----------------
__global__ void detect_types(const int* __restrict__ trg_w, const int* __restrict__ mask_w) {
    __shared__ int s_odd_nz, s_bin, s_f32;
    if (threadIdx.x == 0) { s_odd_nz = 0; s_bin = 1; s_f32 = 1; }
    __syncthreads();
    for (int i = threadIdx.x; i < (BB * TT) / 2; i += blockDim.x)
        if (trg_w[2 * i + 1] != 0) atomicOr(&s_odd_nz, 1);
    for (int i = threadIdx.x; i < (BB * SS) / 4; i += blockDim.x) {
        int v = mask_w[i];
        if (v != 0 && v != 1)           atomicAnd(&s_bin, 0);
        if (v != 0 && v != 0x3f800000)  atomicAnd(&s_f32, 0);
    }
    __syncthreads();
    if (threadIdx.x == 0) {
        g_trg64 = s_odd_nz ? 0 : 1;
        g_maskty = s_bin ? 1 : (s_f32 ? 2 : 0);
    }
}

// ---------------- prep kernels ----------------
__global__ void prep_w4(const float* __restrict__ Wih, const float* __restrict__ Whh,
                        const float* __restrict__ bih, const float* __restrict__ bhh) {
    int rr = blockIdx.x;
    int h = rr >> 2, g = rr & 3;
    int j = g * HH + h;
    for (int k = threadIdx.x; k < KZ; k += blockDim.x) {
        float v = (k < 2 * EE) ? Wih[j * (2 * EE) + k] : Whh[j * HH + (k - 2 * EE)];
        g_W4[rr * KZ + k] = v;
    }
    if (threadIdx.x == 0) g_b4[rr] = bih[j] + bhh[j];
}

__global__ void prep_wqb(const float* __restrict__ Wq, const float* __restrict__ Wb,
                         const float* __restrict__ bq, const float* __restrict__ bbias) {
    int r = blockIdx.y * 16 + threadIdx.y;
    int c = blockIdx.x * 16 + threadIdx.x;
    float acc = 0.f;
    for (int k = 0; k < HH; k++) acc += Wb[r * HH + k] * Wq[k * HH + c];
    g_Wqb[r * HH + c] = acc;
    if (blockIdx.x == 0 && threadIdx.x == 0) {
        float a = bbias[r];
        for (int k = 0; k < HH; k++) a += Wb[r * HH + k] * bq[k];
        g_bqb[r] = a;
    }
}

__global__ void prep_init(const float* __restrict__ ih, const float* __restrict__ ic) {
    int i = blockIdx.x * 256 + threadIdx.x;
    if (i < BB * HH) { g_h[0][i] = ih[i]; g_c[i] = ic[i]; }
}

// split fp32 -> bf16 hi + bf16 lo (float4 granularity)
__global__ void conv_split(const float* __restrict__ src,
                           unsigned short* __restrict__ hi,
                           unsigned short* __restrict__ lo, int n4) {
    int i = blockIdx.x * 256 + threadIdx.x;
    if (i >= n4) return;
    float4 v = ((const float4*)src)[i];
    __nv_bfloat16 h0 = __float2bfloat16(v.x);
    __nv_bfloat16 h1 = __float2bfloat16(v.y);
    __nv_bfloat16 h2 = __float2bfloat16(v.z);
    __nv_bfloat16 h3 = __float2bfloat16(v.w);
    __nv_bfloat16 l0 = __float2bfloat16(v.x - __bfloat162float(h0));
    __nv_bfloat16 l1 = __float2bfloat16(v.y - __bfloat162float(h1));
    __nv_bfloat16 l2 = __float2bfloat16(v.z - __bfloat162float(h2));
    __nv_bfloat16 l3 = __float2bfloat16(v.w - __bfloat162float(h3));
    __nv_bfloat162* H = (__nv_bfloat162*)hi;
    __nv_bfloat162* L = (__nv_bfloat162*)lo;
    H[2 * i]     = __halves2bfloat162(h0, h1);
    H[2 * i + 1] = __halves2bfloat162(h2, h3);
    L[2 * i]     = __halves2bfloat162(l0, l1);
    L[2 * i + 1] = __halves2bfloat162(l2, l3);
}

// ---------------- per-step kernel 1: gates GEMM + LSTM elementwise ----------------
__global__ void __launch_bounds__(256) lstm_gates(
    const float* __restrict__ emb, const void* __restrict__ trg_raw, int t,
    const float* __restrict__ out_prev, const float* __restrict__ h_prev,
    float* __restrict__ h_out)
{
    __shared__ float Zs[64][33];
    __shared__ float Ws[16][64];
    __shared__ float Gs[16][33];
    __shared__ int   tok[BB];

    int tid = threadIdx.x, w = tid >> 5, l = tid & 31;
    int hg = blockIdx.x;
    int rbase = hg * 16;

    if (tid < BB) {
        long long v;
        if (g_trg64) v = ((const long long*)trg_raw)[tid * TT + t];
        else         v = ((const int*)trg_raw)[tid * TT + t];
        int tk = (int)v;
        if (tk < 0) tk = 0;
        if (tk >= VV) tk = VV - 1;
        tok[tid] = tk;
    }
    __syncthreads();

    float acc0 = 0.f, acc1 = 0.f;
    for (int kt = 0; kt < KZ / 64; kt++) {
        int kg0 = kt * 64;
        for (int i = tid; i < 2048; i += 256) {
            int b = i >> 6, k = i & 63, kg = kg0 + k;
            float v;
            if      (kg < EE)      v = emb[(size_t)tok[b] * EE + kg];
            else if (kg < 2 * EE)  v = out_prev[b * EE + (kg - EE)];
            else                   v = h_prev[b * HH + (kg - 2 * EE)];
            Zs[k][b] = v;
        }
        for (int i = tid; i < 1024; i += 256) {
            int r = i >> 6, k = i & 63;
            Ws[r][k] = g_W4[(rbase + r) * KZ + kg0 + k];
        }
        __syncthreads();
        #pragma unroll
        for (int kk = 0; kk < 64; kk++) {
            float z = Zs[kk][l];
            acc0 += Ws[w][kk] * z;
            acc1 += Ws[w + 8][kk] * z;
        }
        __syncthreads();
    }
    Gs[w][l]     = acc0 + g_b4[rbase + w];
    Gs[w + 8][l] = acc1 + g_b4[rbase + w + 8];
    __syncthreads();

    if (tid < 128) {
        int hl = tid >> 5, b = tid & 31;
        float gi = Gs[4 * hl + 0][b];
        float gf = Gs[4 * hl + 1][b];
        float gg = Gs[4 * hl + 2][b];
        float go = Gs[4 * hl + 3][b];
        gi = 1.f / (1.f + expf(-gi));
        gf = 1.f / (1.f + expf(-gf));
        go = 1.f / (1.f + expf(-go));
        gg = tanhf(gg);
        int h = hg * 4 + hl;
        int idx = b * HH + h;
        float c = gf * g_c[idx] + gi * gg;
        g_c[idx] = c;
        h_out[idx] = go * tanhf(c);
    }
}

// ---------------- generic small GEMM: out(32,M) = Z(32,Ktot) @ W(M,Ktot)^T + bias ---------------
__global__ void __launch_bounds__(256) gemm16(
    const float* __restrict__ W, const float* __restrict__ bias,
    const float* __restrict__ Z0, int K0,
    const float* __restrict__ Z1, int Ktot,
    float* __restrict__ outp, int M, int act)
{
    __shared__ float Zs[64][33];
    __shared__ float Ws[16][64];
    int tid = threadIdx.x, w = tid >> 5, l = tid & 31;
    int rbase = blockIdx.x * 16;

    float acc0 = 0.f, acc1 = 0.f;
    for (int kt = 0; kt < Ktot / 64; kt++) {
        int kg0 = kt * 64;
        for (int i = tid; i < 2048; i += 256) {
            int b = i >> 6, k = i & 63, kg = kg0 + k;
            float v = (kg < K0) ? Z0[b * K0 + kg] : Z1[b * (Ktot - K0) + (kg - K0)];
            Zs[k][b] = v;
        }
        for (int i = tid; i < 1024; i += 256) {
            int r = i >> 6, k = i & 63;
            Ws[r][k] = W[(rbase + r) * Ktot + kg0 + k];
        }
        __syncthreads();
        #pragma unroll
        for (int kk = 0; kk < 64; kk++) {
            float z = Zs[kk][l];
            acc0 += Ws[w][kk] * z;
            acc1 += Ws[w + 8][kk] * z;
        }
        __syncthreads();
    }
    acc0 += bias[rbase + w];
    acc1 += bias[rbase + w + 8];
    if (act) { acc0 = tanhf(acc0); acc1 = tanhf(acc1); }
    outp[l * M + rbase + w]     = acc0;
    outp[l * M + rbase + w + 8] = acc1;
}

// ---------------- attention ----------------
__global__ void __launch_bounds__(256) attention(
    const float* __restrict__ mem, const void* __restrict__ mask_raw)
{
    int b = blockIdx.x, tid = threadIdx.x, w = tid >> 5, l = tid & 31;
    __shared__ float q[HH];
    __shared__ float sc[SS];

    for (int i = tid; i < HH; i += 256) q[i] = g_qb[b * HH + i];
    __syncthreads();

    int mty = g_maskty;
    for (int s = w; s < SS; s += 8) {
        const float* mrow = mem + (size_t)(b * SS + s) * HH;
        float a = 0.f;
        for (int k = l; k < HH; k += 32) a += q[k] * mrow[k];
        #pragma unroll
        for (int off = 16; off; off >>= 1) a += __shfl_down_sync(0xffffffffu, a, off);
        if (l == 0) {
            int mi = b * SS + s;
            bool mv;
            if      (mty == 0) mv = ((const unsigned char*)mask_raw)[mi] != 0;
            else if (mty == 1) mv = ((const int*)mask_raw)[mi] != 0;
            else               mv = ((const float*)mask_raw)[mi] != 0.0f;
            sc[s] = mv ? a : -1e9f;
        }
    }
    __syncthreads();

    if (w == 0) {
        float m = -1e30f;
        for (int s = l; s < SS; s += 32) m = fmaxf(m, sc[s]);
        #pragma unroll
        for (int off = 16; off; off >>= 1) m = fmaxf(m, __shfl_xor_sync(0xffffffffu, m, off));
        float sum = 0.f;
        for (int s = l; s < SS; s += 32) { float e = expf(sc[s] - m); sc[s] = e; sum += e; }
        #pragma unroll
        for (int off = 16; off; off >>= 1) sum += __shfl_xor_sync(0xffffffffu, sum, off);
        float inv = 1.f / sum;
        for (int s = l; s < SS; s += 32) sc[s] *= inv;
    }
    __syncthreads();

    for (int h = tid; h < HH; h += 256) {
        float a = 0.f;
        #pragma unroll 4
        for (int s = 0; s < SS; s++) a += sc[s] * mem[(size_t)(b * SS + s) * HH + h];
        g_ctx[b * HH + h] = a;
    }
}

// ---------------- HMMA logits GEMM ----------------
// D(2048,32000) = A(2048,512) @ B(32000,512)^T via bf16 split:
//   3 passes over K=512: (Ah,Bh), (Ah,Bl), (Al,Bh), fp32 accumulate in registers.
// CTA tile 128x128, K-chunk 64. Warps: 2(M) x 4(N) -> 64x32 warp tiles.
// Smem rows padded to 72 bf16 (144B) -> conflict-free ldmatrix.
#define SPAD 72
__global__ void __launch_bounds__(256, 2) logits_mma(float* __restrict__ outp)
{
    __shared__ __align__(16) unsigned short sA[128 * SPAD];
    __shared__ __align__(16) unsigned short sB[128 * SPAD];

    int tid = threadIdx.x, lane = tid & 31, wid = tid >> 5;
    int wm = wid >> 2;            // 0..1 (64 M rows each)
    int wn = wid & 3;             // 0..3 (32 N cols each)
    int mblk = blockIdx.x * 128;  // x fastest: 16 M-tiles share one B tile in L2
    int nblk = blockIdx.y * 128;

    uint32_t aA = smem_u32(sA);
    uint32_t aB = smem_u32(sB);
    // ldmatrix per-lane base addresses (bytes): row = lane&15, half = lane>>4 (+16B)
    uint32_t abase = aA + (uint32_t)((wm * 64 + (lane & 15)) * SPAD * 2 + (lane >> 4) * 16);
    uint32_t bbase = aB + (uint32_t)((wn * 32 + (lane & 15)) * SPAD * 2 + (lane >> 4) * 16);

    float acc[4][4][4];
    #pragma unroll
    for (int i = 0; i < 4; i++)
        #pragma unroll
        for (int j = 0; j < 4; j++)
            #pragma unroll
            for (int k = 0; k < 4; k++) acc[i][j][k] = 0.f;

    for (int c = 0; c < 24; c++) {
        int pass = c >> 3;
        int kb = (c & 7) * 64;
        const unsigned short* Ap = (pass == 2) ? g_Al : g_Ah;
        const unsigned short* Bp = (pass == 1) ? g_Bl : g_Bh;

        __syncthreads();   // protect smem from previous iteration's readers
        // Load 128x64 bf16 tiles: 1024 uint4 each, 4 per thread, coalesced.
        #pragma unroll
        for (int u = 0; u < 4; u++) {
            int unit = u * 256 + tid;        // 0..1023
            int row = unit >> 3, seg = unit & 7;
            uint4 va = *(const uint4*)(Ap + (size_t)(mblk + row) * 512 + kb + seg * 8);
            *(uint4*)(sA + row * SPAD + seg * 8) = va;
            uint4 vb = *(const uint4*)(Bp + (size_t)(nblk + row) * 512 + kb + seg * 8);
            *(uint4*)(sB + row * SPAD + seg * 8) = vb;
        }
        __syncthreads();

        #pragma unroll
        for (int ks = 0; ks < 4; ks++) {
            uint32_t afr[4][4];
            #pragma unroll
            for (int mf = 0; mf < 4; mf++)
                ldm_x4(afr[mf], abase + (uint32_t)(mf * 16 * SPAD * 2 + ks * 32));
            uint32_t bfr[2][4];
            #pragma unroll
            for (int g = 0; g < 2; g++)
                ldm_x4(bfr[g], bbase + (uint32_t)(g * 16 * SPAD * 2 + ks * 32));
            #pragma unroll
            for (int mf = 0; mf < 4; mf++)
                #pragma unroll
                for (int nf = 0; nf < 4; nf++)
                    mma_bf16(acc[mf][nf], afr[mf],
                             bfr[nf >> 1][nf & 1], bfr[nf >> 1][(nf & 1) + 2]);
        }
    }

    // Epilogue: D row r = t*B + b -> out[(b*T + t)*V + col]
    #pragma unroll
    for (int mf = 0; mf < 4; mf++) {
        int r0 = mblk + wm * 64 + mf * 16 + (lane >> 2);
        #pragma unroll
        for (int half = 0; half < 2; half++) {
            int r = r0 + half * 8;
            int tt = r >> 5, b2 = r & 31;
            float* orow = outp + (size_t)(b2 * TT + tt) * VV + nblk + wn * 32 + (lane & 3) * 2;
            #pragma unroll
            for (int nf = 0; nf < 4; nf++) {
                float2 v = make_float2(acc[mf][nf][2 * half], acc[mf][nf][2 * half + 1]);
                *(float2*)(orow + nf * 8) = v;
            }
        }
    }
}

// ---------------- host launch ----------------
extern "C" void kernel_launch(void* const* d_in, const int* in_sizes, int n_in,
                              void* d_out, int out_size)
{
    const float* src_memory  = (const float*)d_in[0];
    const void*  src_mask    = d_in[1];
    const float* init_hidden = (const float*)d_in[2];
    const float* init_cell   = (const float*)d_in[3];
    const float* init_output = (const float*)d_in[4];
    const void*  trg         = d_in[5];
    const float* emb         = (const float*)d_in[6];
    const float* W_ih        = (const float*)d_in[7];
    const float* W_hh        = (const float*)d_in[8];
    const float* b_ih        = (const float*)d_in[9];
    const float* b_hh        = (const float*)d_in[10];
    const float* Wq          = (const float*)d_in[11];
    const float* bq          = (const float*)d_in[12];
    const float* Wb          = (const float*)d_in[13];
    const float* bbias       = (const float*)d_in[14];
    const float* Wo1         = (const float*)d_in[15];
    const float* bo1         = (const float*)d_in[16];
    const float* Wo2         = (const float*)d_in[17];
    const float* bo2         = (const float*)d_in[18];

    float *p_Wqb, *p_bqb, *p_h, *p_qb, *p_ctx, *p_u, *p_out;
    unsigned short *p_Bh, *p_Bl, *p_Ah, *p_Al;
    cudaGetSymbolAddress((void**)&p_Wqb, g_Wqb);
    cudaGetSymbolAddress((void**)&p_bqb, g_bqb);
    cudaGetSymbolAddress((void**)&p_h,   g_h);
    cudaGetSymbolAddress((void**)&p_qb,  g_qb);
    cudaGetSymbolAddress((void**)&p_ctx, g_ctx);
    cudaGetSymbolAddress((void**)&p_u,   g_u);
    cudaGetSymbolAddress((void**)&p_out, g_out);
    cudaGetSymbolAddress((void**)&p_Bh,  g_Bh);
    cudaGetSymbolAddress((void**)&p_Bl,  g_Bl);
    cudaGetSymbolAddress((void**)&p_Ah,  g_Ah);
    cudaGetSymbolAddress((void**)&p_Al,  g_Al);

    detect_types<<<1, 256>>>((const int*)trg, (const int*)src_mask);
    prep_w4<<<G4H, 256>>>(W_ih, W_hh, b_ih, b_hh);
    prep_wqb<<<dim3(32, 32), dim3(16, 16)>>>(Wq, Wb, bq, bbias);
    prep_init<<<(BB * HH + 255) / 256, 256>>>(init_hidden, init_cell);

    // emb -> bf16 hi/lo (16.384M elems)
    {
        int n4 = (VV * EE) / 4;
        conv_split<<<(n4 + 255) / 256, 256>>>(emb, p_Bh, p_Bl, n4);
    }

    for (int t = 0; t < TT; t++) {
        const float* out_prev = (t == 0) ? init_output : (p_out + (size_t)(t - 1) * BB * EE);
        const float* h_prev = p_h + (t & 1) * BB * HH;
        float*       h_cur  = p_h + ((t + 1) & 1) * BB * HH;

        lstm_gates<<<128, 256>>>(emb, trg, t, out_prev, h_prev, h_cur);
        gemm16<<<HH / 16, 256>>>(p_Wqb, p_bqb, h_cur, HH, (const float*)0, HH, p_qb, HH, 0);
        attention<<<BB, 256>>>(src_memory, src_mask);
        gemm16<<<HH / 16, 256>>>(Wo1, bo1, h_cur, HH, p_ctx, 2 * HH, p_u, HH, 1);
        gemm16<<<HH / 16, 256>>>(Wo2, bo2, p_u, HH, (const float*)0, HH,
                                 p_out + (size_t)t * BB * EE, HH, 0);
    }

    // out -> bf16 hi/lo, then HMMA logits GEMM
    {
        int n4 = (TT * BB * EE) / 4;
        conv_split<<<(n4 + 255) / 256, 256>>>(p_out, p_Ah, p_Al, n4);
    }
    logits_mma<<<dim3(16, 250), 256>>>((float*)d_out);
}

// round 6
// speedup vs baseline: 1.4074x; 1.3017x over previous
#include <cuda_runtime.h>
#include <cuda_bf16.h>
#include <math.h>
#include <stdint.h>

// Problem dims
#define BB  32      // batch
#define SS  100     // src len
#define TT  64      // trg len
#define HH  512     // hidden
#define EE  512     // embed
#define VV  32000   // vocab
#define G4H 2048    // 4*H
#define KZ  1536    // 2E + H (fused gate input)
#define NBLK 128    // persistent-kernel grid (co-resident on 148 SMs)

// ---------------- device scratch (static globals; no runtime alloc) ----------------
__device__ float g_W4[G4H * KZ];     // fused [W_ih | W_hh], rows reordered to 4*h+gate
__device__ float g_b4[G4H];          // fused bias, same reorder
__device__ float g_Wqb[HH * HH];     // Wb @ Wq
__device__ float g_bqb[HH];          // Wb @ bq + bb
__device__ float g_P[BB * SS * HH];  // Wqb^T-projected memory (step-invariant)
__device__ float g_q0[BB * SS];      // bqb . mem (+ mask folded as -1e9)
__device__ float g_h[2][BB * HH];    // hidden ping-pong
__device__ float g_c[BB * HH];       // cell
__device__ float g_ctx[BB * HH];     // attention context
__device__ float g_u[BB * HH];       // tanh(MLP) intermediate
__device__ float g_out[TT * BB * EE];// all decoder outputs (T,B,E)
__device__ int   g_trg64;            // 1 if trg buffer is int64
__device__ int   g_maskty;           // 0=uint8, 1=int32, 2=float32

// grid barrier state (monotonic generation across graph replays; wrap-safe)
__device__ volatile unsigned g_cnt;
__device__ volatile unsigned g_gen;

// bf16 hi/lo splits for tensor-core logits GEMM
__device__ unsigned short g_Bh[(size_t)VV * EE];  // emb hi
__device__ unsigned short g_Bl[(size_t)VV * EE];  // emb lo
__device__ unsigned short g_Ah[(size_t)TT * BB * EE]; // out hi
__device__ unsigned short g_Al[(size_t)TT * BB * EE]; // out lo

// ---------------- helpers ----------------
__device__ __forceinline__ uint32_t smem_u32(const void* p) {
    uint32_t a;
    asm("{ .reg .u64 t; cvta.to.shared.u64 t, %1; cvt.u32.u64 %0, t; }" : "=r"(a) : "l"(p));
    return a;
}

__device__ __forceinline__ void ldm_x4(uint32_t* r, uint32_t addr) {
    asm volatile("ldmatrix.sync.aligned.m8n8.x4.shared.b16 {%0,%1,%2,%3}, [%4];"
                 : "=r"(r[0]), "=r"(r[1]), "=r"(r[2]), "=r"(r[3]) : "r"(addr));
}

__device__ __forceinline__ void mma_bf16(float* d, const uint32_t* a, uint32_t b0, uint32_t b1) {
    asm volatile(
        "mma.sync.aligned.m16n8k16.row.col.f32.bf16.bf16.f32 "
        "{%0,%1,%2,%3}, {%4,%5,%6,%7}, {%8,%9}, {%0,%1,%2,%3};"
        : "+f"(d[0]), "+f"(d[1]), "+f"(d[2]), "+f"(d[3])
        : "r"(a[0]), "r"(a[1]), "r"(a[2]), "r"(a[3]), "r"(b0), "r"(b1));
}

// sense-reversing grid barrier (all NBLK blocks co-resident)
__device__ __forceinline__ void gsync() {
    __syncthreads();
    if (threadIdx.x == 0) {
        unsigned gen = g_gen;
        __threadfence();
        if (atomicAdd((unsigned*)&g_cnt, 1u) == NBLK - 1) {
            g_cnt = 0;
            __threadfence();
            g_gen = gen + 1;
        } else {
            while (g_gen == gen) __nanosleep(20);
        }
        __threadfence();
    }
    __syncthreads();
}

// ---------------- dtype detection (graph-safe, runs every call) ----------------
__global__ void detect_types(const int* __restrict__ trg_w, const int* __restrict__ mask_w) {
    __shared__ int s_odd_nz, s_bin, s_f32;
    if (threadIdx.x == 0) { s_odd_nz = 0; s_bin = 1; s_f32 = 1; }
    __syncthreads();
    for (int i = threadIdx.x; i < (BB * TT) / 2; i += blockDim.x)
        if (trg_w[2 * i + 1] != 0) atomicOr(&s_odd_nz, 1);
    for (int i = threadIdx.x; i < (BB * SS) / 4; i += blockDim.x) {
        int v = mask_w[i];
        if (v != 0 && v != 1)           atomicAnd(&s_bin, 0);
        if (v != 0 && v != 0x3f800000)  atomicAnd(&s_f32, 0);
    }
    __syncthreads();
    if (threadIdx.x == 0) {
        g_trg64 = s_odd_nz ? 0 : 1;
        g_maskty = s_bin ? 1 : (s_f32 ? 2 : 0);
    }
}

// ---------------- prep kernels ----------------
__global__ void prep_w4(const float* __restrict__ Wih, const float* __restrict__ Whh,
                        const float* __restrict__ bih, const float* __restrict__ bhh) {
    int rr = blockIdx.x;
    int h = rr >> 2, g = rr & 3;
    int j = g * HH + h;
    for (int k = threadIdx.x; k < KZ; k += blockDim.x) {
        float v = (k < 2 * EE) ? Wih[j * (2 * EE) + k] : Whh[j * HH + (k - 2 * EE)];
        g_W4[rr * KZ + k] = v;
    }
    if (threadIdx.x == 0) g_b4[rr] = bih[j] + bhh[j];
}

__global__ void prep_wqb(const float* __restrict__ Wq, const float* __restrict__ Wb,
                         const float* __restrict__ bq, const float* __restrict__ bbias) {
    int r = blockIdx.y * 16 + threadIdx.y;
    int c = blockIdx.x * 16 + threadIdx.x;
    float acc = 0.f;
    for (int k = 0; k < HH; k++) acc += Wb[r * HH + k] * Wq[k * HH + c];
    g_Wqb[r * HH + c] = acc;
    if (blockIdx.x == 0 && threadIdx.x == 0) {
        float a = bbias[r];
        for (int k = 0; k < HH; k++) a += Wb[r * HH + k] * bq[k];
        g_bqb[r] = a;
    }
}

__global__ void prep_init(const float* __restrict__ ih, const float* __restrict__ ic) {
    int i = blockIdx.x * 256 + threadIdx.x;
    if (i < BB * HH) { g_h[0][i] = ih[i]; g_c[i] = ic[i]; }
}

// split fp32 -> bf16 hi + bf16 lo (float4 granularity)
__global__ void conv_split(const float* __restrict__ src,
                           unsigned short* __restrict__ hi,
                           unsigned short* __restrict__ lo, int n4) {
    int i = blockIdx.x * 256 + threadIdx.x;
    if (i >= n4) return;
    float4 v = ((const float4*)src)[i];
    __nv_bfloat16 h0 = __float2bfloat16(v.x);
    __nv_bfloat16 h1 = __float2bfloat16(v.y);
    __nv_bfloat16 h2 = __float2bfloat16(v.z);
    __nv_bfloat16 h3 = __float2bfloat16(v.w);
    __nv_bfloat16 l0 = __float2bfloat16(v.x - __bfloat162float(h0));
    __nv_bfloat16 l1 = __float2bfloat16(v.y - __bfloat162float(h1));
    __nv_bfloat16 l2 = __float2bfloat16(v.z - __bfloat162float(h2));
    __nv_bfloat16 l3 = __float2bfloat16(v.w - __bfloat162float(h3));
    __nv_bfloat162* H = (__nv_bfloat162*)hi;
    __nv_bfloat162* L = (__nv_bfloat162*)lo;
    H[2 * i]     = __halves2bfloat162(h0, h1);
    H[2 * i + 1] = __halves2bfloat162(h2, h3);
    L[2 * i]     = __halves2bfloat162(l0, l1);
    L[2 * i + 1] = __halves2bfloat162(l2, l3);
}

// ---------------- P = mem_flat(3200,512) @ Wqb(512,512)  (fp32 tiled GEMM) ----------------
__global__ void __launch_bounds__(256) pgemm(const float* __restrict__ mem) {
    __shared__ float As[16][68];
    __shared__ float Bs[16][68];
    int tid = threadIdx.x;
    int m0 = blockIdx.y * 64, j0 = blockIdx.x * 64;
    int tx = tid & 15, ty = tid >> 4;

    float acc[4][4];
    #pragma unroll
    for (int i = 0; i < 4; i++)
        #pragma unroll
        for (int j = 0; j < 4; j++) acc[i][j] = 0.f;

    for (int k0 = 0; k0 < HH; k0 += 16) {
        int row = tid >> 2, kq = (tid & 3) * 4;
        float4 va = *(const float4*)(mem + (size_t)(m0 + row) * HH + k0 + kq);
        As[kq][row] = va.x; As[kq + 1][row] = va.y;
        As[kq + 2][row] = va.z; As[kq + 3][row] = va.w;
        int kr = tid >> 4, jq = (tid & 15) * 4;
        float4 vb = *(const float4*)(g_Wqb + (size_t)(k0 + kr) * HH + j0 + jq);
        *(float4*)&Bs[kr][jq] = vb;
        __syncthreads();
        #pragma unroll
        for (int k = 0; k < 16; k++) {
            float a[4], b[4];
            #pragma unroll
            for (int i = 0; i < 4; i++) a[i] = As[k][ty * 4 + i];
            #pragma unroll
            for (int i = 0; i < 4; i++) b[i] = Bs[k][tx * 4 + i];
            #pragma unroll
            for (int i = 0; i < 4; i++)
                #pragma unroll
                for (int j = 0; j < 4; j++) acc[i][j] += a[i] * b[j];
        }
        __syncthreads();
    }
    #pragma unroll
    for (int i = 0; i < 4; i++)
        #pragma unroll
        for (int j = 0; j < 4; j++)
            g_P[(size_t)(m0 + ty * 4 + i) * HH + j0 + tx * 4 + j] = acc[i][j];
}

// q0[m] = bqb . mem[m]  (mask folded: masked -> -1e9). m = b*SS + s matches mask layout.
__global__ void q0_kernel(const float* __restrict__ mem, const void* __restrict__ mask_raw) {
    int m = blockIdx.x * 8 + (threadIdx.x >> 5);
    int l = threadIdx.x & 31;
    if (m >= BB * SS) return;
    float a = 0.f;
    for (int k = l; k < HH; k += 32) a += g_bqb[k] * mem[(size_t)m * HH + k];
    #pragma unroll
    for (int off = 16; off; off >>= 1) a += __shfl_down_sync(0xffffffffu, a, off);
    if (l == 0) {
        int mty = g_maskty;
        bool mv;
        if      (mty == 0) mv = ((const unsigned char*)mask_raw)[m] != 0;
        else if (mty == 1) mv = ((const int*)mask_raw)[m] != 0;
        else               mv = ((const float*)mask_raw)[m] != 0.0f;
        g_q0[m] = mv ? a : -1e9f;
    }
}

// ---------------- persistent decoder loop: all 64 steps in ONE kernel ----------------
__global__ void __launch_bounds__(256) decoder_loop(
    const float* __restrict__ emb, const void* __restrict__ trg_raw,
    const float* __restrict__ mem, const float* __restrict__ init_output,
    const float* __restrict__ Wo1, const float* __restrict__ bo1,
    const float* __restrict__ Wo2, const float* __restrict__ bo2)
{
    __shared__ union {
        struct { float Zs[64][33]; float Ws[16][64]; float Gs[16][33]; int tok[BB]; } a;
        struct { float q[HH]; float sc[128]; } c;
        struct { float Zs[64][33]; float Ws[4][64]; } d;
    } sm;

    int tid = threadIdx.x, wid = tid >> 5, lane = tid & 31;
    int bid = blockIdx.x;

    for (int t = 0; t < TT; t++) {
        const float* out_prev = (t == 0) ? init_output : (g_out + (size_t)(t - 1) * BB * EE);
        const float* h_prev = g_h[t & 1];
        float*       h_cur  = g_h[(t + 1) & 1];

        // ---- Phase A: gates GEMM + LSTM elementwise (block bid -> 16 gate rows) ----
        {
            int rbase = bid * 16;
            if (tid < BB) {
                long long v;
                if (g_trg64) v = ((const long long*)trg_raw)[tid * TT + t];
                else         v = ((const int*)trg_raw)[tid * TT + t];
                int tk = (int)v;
                if (tk < 0) tk = 0;
                if (tk >= VV) tk = VV - 1;
                sm.a.tok[tid] = tk;
            }
            __syncthreads();

            float acc0 = 0.f, acc1 = 0.f;
            for (int kt = 0; kt < KZ / 64; kt++) {
                int kg0 = kt * 64;
                for (int i = tid; i < 2048; i += 256) {
                    int b = i >> 6, k = i & 63, kg = kg0 + k;
                    float v;
                    if      (kg < EE)      v = emb[(size_t)sm.a.tok[b] * EE + kg];
                    else if (kg < 2 * EE)  v = out_prev[b * EE + (kg - EE)];
                    else                   v = h_prev[b * HH + (kg - 2 * EE)];
                    sm.a.Zs[k][b] = v;
                }
                for (int i = tid; i < 1024; i += 256) {
                    int r = i >> 6, k = i & 63;
                    sm.a.Ws[r][k] = g_W4[(rbase + r) * KZ + kg0 + k];
                }
                __syncthreads();
                #pragma unroll
                for (int kk = 0; kk < 64; kk++) {
                    float z = sm.a.Zs[kk][lane];
                    acc0 += sm.a.Ws[wid][kk] * z;
                    acc1 += sm.a.Ws[wid + 8][kk] * z;
                }
                __syncthreads();
            }
            sm.a.Gs[wid][lane]     = acc0 + g_b4[rbase + wid];
            sm.a.Gs[wid + 8][lane] = acc1 + g_b4[rbase + wid + 8];
            __syncthreads();

            if (tid < 128) {
                int hl = tid >> 5, b = tid & 31;
                float gi = sm.a.Gs[4 * hl + 0][b];
                float gf = sm.a.Gs[4 * hl + 1][b];
                float gg = sm.a.Gs[4 * hl + 2][b];
                float go = sm.a.Gs[4 * hl + 3][b];
                gi = 1.f / (1.f + expf(-gi));
                gf = 1.f / (1.f + expf(-gf));
                go = 1.f / (1.f + expf(-go));
                gg = tanhf(gg);
                int h = bid * 4 + hl;
                int idx = b * HH + h;
                float c = gf * g_c[idx] + gi * gg;
                g_c[idx] = c;
                h_cur[idx] = go * tanhf(c);
            }
        }
        gsync();

        // ---- Phase C: attention (blocks 0..31, one per batch) ----
        if (bid < BB) {
            int b = bid;
            for (int i = tid; i < HH; i += 256) sm.c.q[i] = h_cur[b * HH + i];
            __syncthreads();

            for (int s = wid; s < SS; s += 8) {
                const float* prow = g_P + (size_t)(b * SS + s) * HH;
                float a = 0.f;
                for (int k = lane; k < HH; k += 32) a += sm.c.q[k] * prow[k];
                #pragma unroll
                for (int off = 16; off; off >>= 1) a += __shfl_down_sync(0xffffffffu, a, off);
                if (lane == 0) sm.c.sc[s] = a + g_q0[b * SS + s];
            }
            __syncthreads();

            if (wid == 0) {
                float m = -1e30f;
                for (int s = lane; s < SS; s += 32) m = fmaxf(m, sm.c.sc[s]);
                #pragma unroll
                for (int off = 16; off; off >>= 1) m = fmaxf(m, __shfl_xor_sync(0xffffffffu, m, off));
                float sum = 0.f;
                for (int s = lane; s < SS; s += 32) {
                    float e = expf(sm.c.sc[s] - m); sm.c.sc[s] = e; sum += e;
                }
                #pragma unroll
                for (int off = 16; off; off >>= 1) sum += __shfl_xor_sync(0xffffffffu, sum, off);
                float inv = 1.f / sum;
                for (int s = lane; s < SS; s += 32) sm.c.sc[s] *= inv;
            }
            __syncthreads();

            for (int h = tid; h < HH; h += 256) {
                float a = 0.f;
                #pragma unroll 4
                for (int s = 0; s < SS; s++) a += sm.c.sc[s] * mem[(size_t)(b * SS + s) * HH + h];
                g_ctx[b * HH + h] = a;
            }
        }
        gsync();

        // ---- Phase D1: u = tanh(Wo1 [h|ctx] + bo1)  (block -> 4 rows x 32 b, K=1024) ----
        {
            int r0 = bid * 4;
            float acc = 0.f;
            for (int kt = 0; kt < 16; kt++) {
                int kg0 = kt * 64;
                for (int i = tid; i < 2048; i += 256) {
                    int b = i >> 6, k = i & 63, kg = kg0 + k;
                    float v = (kg < HH) ? h_cur[b * HH + kg] : g_ctx[b * HH + (kg - HH)];
                    sm.d.Zs[k][b] = v;
                }
                if (tid < 256) {
                    int r = tid >> 6, k = tid & 63;
                    sm.d.Ws[r][k] = Wo1[(size_t)(r0 + r) * (2 * HH) + kg0 + k];
                }
                __syncthreads();
                if (wid < 4) {
                    #pragma unroll
                    for (int kk = 0; kk < 64; kk++)
                        acc += sm.d.Ws[wid][kk] * sm.d.Zs[kk][lane];
                }
                __syncthreads();
            }
            if (wid < 4)
                g_u[lane * HH + r0 + wid] = tanhf(acc + bo1[r0 + wid]);
        }
        gsync();

        // ---- Phase D2: out = Wo2 u + bo2  (block -> 4 rows x 32 b, K=512) ----
        {
            int r0 = bid * 4;
            float acc = 0.f;
            for (int kt = 0; kt < 8; kt++) {
                int kg0 = kt * 64;
                for (int i = tid; i < 2048; i += 256) {
                    int b = i >> 6, k = i & 63;
                    sm.d.Zs[k][b] = g_u[b * HH + kg0 + k];
                }
                if (tid < 256) {
                    int r = tid >> 6, k = tid & 63;
                    sm.d.Ws[r][k] = Wo2[(size_t)(r0 + r) * HH + kg0 + k];
                }
                __syncthreads();
                if (wid < 4) {
                    #pragma unroll
                    for (int kk = 0; kk < 64; kk++)
                        acc += sm.d.Ws[wid][kk] * sm.d.Zs[kk][lane];
                }
                __syncthreads();
            }
            if (wid < 4)
                g_out[((size_t)t * BB + lane) * EE + r0 + wid] = acc + bo2[r0 + wid];
        }
        gsync();
    }
}

// ---------------- HMMA logits GEMM ----------------
// D(2048,32000) = A(2048,512) @ B(32000,512)^T via bf16 split:
//   3 passes over K=512: (Ah,Bh), (Ah,Bl), (Al,Bh), fp32 accumulate in registers.
#define SPAD 72
__global__ void __launch_bounds__(256, 2) logits_mma(float* __restrict__ outp)
{
    __shared__ __align__(16) unsigned short sA[128 * SPAD];
    __shared__ __align__(16) unsigned short sB[128 * SPAD];

    int tid = threadIdx.x, lane = tid & 31, wid = tid >> 5;
    int wm = wid >> 2;
    int wn = wid & 3;
    int mblk = blockIdx.x * 128;
    int nblk = blockIdx.y * 128;

    uint32_t aA = smem_u32(sA);
    uint32_t aB = smem_u32(sB);
    uint32_t abase = aA + (uint32_t)((wm * 64 + (lane & 15)) * SPAD * 2 + (lane >> 4) * 16);
    uint32_t bbase = aB + (uint32_t)((wn * 32 + (lane & 15)) * SPAD * 2 + (lane >> 4) * 16);

    float acc[4][4][4];
    #pragma unroll
    for (int i = 0; i < 4; i++)
        #pragma unroll
        for (int j = 0; j < 4; j++)
            #pragma unroll
            for (int k = 0; k < 4; k++) acc[i][j][k] = 0.f;

    for (int c = 0; c < 24; c++) {
        int pass = c >> 3;
        int kb = (c & 7) * 64;
        const unsigned short* Ap = (pass == 2) ? g_Al : g_Ah;
        const unsigned short* Bp = (pass == 1) ? g_Bl : g_Bh;

        __syncthreads();
        #pragma unroll
        for (int u = 0; u < 4; u++) {
            int unit = u * 256 + tid;
            int row = unit >> 3, seg = unit & 7;
            uint4 va = *(const uint4*)(Ap + (size_t)(mblk + row) * 512 + kb + seg * 8);
            *(uint4*)(sA + row * SPAD + seg * 8) = va;
            uint4 vb = *(const uint4*)(Bp + (size_t)(nblk + row) * 512 + kb + seg * 8);
            *(uint4*)(sB + row * SPAD + seg * 8) = vb;
        }
        __syncthreads();

        #pragma unroll
        for (int ks = 0; ks < 4; ks++) {
            uint32_t afr[4][4];
            #pragma unroll
            for (int mf = 0; mf < 4; mf++)
                ldm_x4(afr[mf], abase + (uint32_t)(mf * 16 * SPAD * 2 + ks * 32));
            uint32_t bfr[2][4];
            #pragma unroll
            for (int g = 0; g < 2; g++)
                ldm_x4(bfr[g], bbase + (uint32_t)(g * 16 * SPAD * 2 + ks * 32));
            #pragma unroll
            for (int mf = 0; mf < 4; mf++)
                #pragma unroll
                for (int nf = 0; nf < 4; nf++)
                    mma_bf16(acc[mf][nf], afr[mf],
                             bfr[nf >> 1][nf & 1], bfr[nf >> 1][(nf & 1) + 2]);
        }
    }

    #pragma unroll
    for (int mf = 0; mf < 4; mf++) {
        int r0 = mblk + wm * 64 + mf * 16 + (lane >> 2);
        #pragma unroll
        for (int half = 0; half < 2; half++) {
            int r = r0 + half * 8;
            int tt = r >> 5, b2 = r & 31;
            float* orow = outp + (size_t)(b2 * TT + tt) * VV + nblk + wn * 32 + (lane & 3) * 2;
            #pragma unroll
            for (int nf = 0; nf < 4; nf++) {
                float2 v = make_float2(acc[mf][nf][2 * half], acc[mf][nf][2 * half + 1]);
                *(float2*)(orow + nf * 8) = v;
            }
        }
    }
}

// ---------------- host launch ----------------
extern "C" void kernel_launch(void* const* d_in, const int* in_sizes, int n_in,
                              void* d_out, int out_size)
{
    const float* src_memory  = (const float*)d_in[0];
    const void*  src_mask    = d_in[1];
    const float* init_hidden = (const float*)d_in[2];
    const float* init_cell   = (const float*)d_in[3];
    const float* init_output = (const float*)d_in[4];
    const void*  trg         = d_in[5];
    const float* emb         = (const float*)d_in[6];
    const float* W_ih        = (const float*)d_in[7];
    const float* W_hh        = (const float*)d_in[8];
    const float* b_ih        = (const float*)d_in[9];
    const float* b_hh        = (const float*)d_in[10];
    const float* Wq          = (const float*)d_in[11];
    const float* bq          = (const float*)d_in[12];
    const float* Wb          = (const float*)d_in[13];
    const float* bbias       = (const float*)d_in[14];
    const float* Wo1         = (const float*)d_in[15];
    const float* bo1         = (const float*)d_in[16];
    const float* Wo2         = (const float*)d_in[17];
    const float* bo2         = (const float*)d_in[18];

    float *p_out;
    unsigned short *p_Bh, *p_Bl, *p_Ah, *p_Al;
    cudaGetSymbolAddress((void**)&p_out, g_out);
    cudaGetSymbolAddress((void**)&p_Bh,  g_Bh);
    cudaGetSymbolAddress((void**)&p_Bl,  g_Bl);
    cudaGetSymbolAddress((void**)&p_Ah,  g_Ah);
    cudaGetSymbolAddress((void**)&p_Al,  g_Al);

    detect_types<<<1, 256>>>((const int*)trg, (const int*)src_mask);
    prep_w4<<<G4H, 256>>>(W_ih, W_hh, b_ih, b_hh);
    prep_wqb<<<dim3(32, 32), dim3(16, 16)>>>(Wq, Wb, bq, bbias);
    prep_init<<<(BB * HH + 255) / 256, 256>>>(init_hidden, init_cell);

    // emb -> bf16 hi/lo
    {
        int n4 = (VV * EE) / 4;
        conv_split<<<(n4 + 255) / 256, 256>>>(emb, p_Bh, p_Bl, n4);
    }

    // attention precompute: P = mem @ Wqb ; q0 = bqb.mem (mask folded)
    pgemm<<<dim3(HH / 64, (BB * SS) / 64), 256>>>(src_memory);
    q0_kernel<<<(BB * SS) / 8, 256>>>(src_memory, src_mask);

    // the entire 64-step recurrence in one persistent kernel
    decoder_loop<<<NBLK, 256>>>(emb, trg, src_memory, init_output, Wo1, bo1, Wo2, bo2);

    // out -> bf16 hi/lo, then HMMA logits GEMM
    {
        int n4 = (TT * BB * EE) / 4;
        conv_split<<<(n4 + 255) / 256, 256>>>(p_out, p_Ah, p_Al, n4);
    }
    logits_mma<<<dim3(16, 250), 256>>>((float*)d_out);
}